// round 1
// baseline (speedup 1.0000x reference)
#include <cuda_runtime.h>
#include <cuda_bf16.h>

// Problem constants (shapes fixed by the dataset; runtime sizes read from in_sizes
// where cheap, storage sized to the fixed maxima).
#define NMAX 100000
#define DH   64
#define GMAX 64
#define DOUT 32

// Scratch (__device__ globals: no allocation allowed in kernel_launch).
__device__ __align__(256) float d_Asum[NMAX * DH];  // Sum_{src->i} g[src]
__device__ __align__(256) float d_g[NMAX * DH];     // dinv[i] * (h1[i] @ W2)
__device__ float d_dinv[NMAX];
__device__ float d_S[NMAX];
__device__ int   d_deg[NMAX];
__device__ float d_v[DH];                            // emb[0] @ W1
__device__ int   d_gstart[GMAX + 2];

// ---------------------------------------------------------------------------
// 0) zero scratch: Asum (N*64 floats), deg, S
__global__ void k_zero(int N) {
    int i = blockIdx.x * blockDim.x + threadIdx.x;
    int n4 = N * (DH / 4);
    if (i < n4) ((float4*)d_Asum)[i] = make_float4(0.f, 0.f, 0.f, 0.f);
    if (i < N) { d_deg[i] = 0; d_S[i] = 0.f; }
}

// 1) in-degree on dst
__global__ void k_deg(const int* __restrict__ ei, int E) {
    int e = blockIdx.x * blockDim.x + threadIdx.x;
    if (e < E) atomicAdd(&d_deg[ei[E + e]], 1);
}

// 2) v = emb[0] @ W1   (one block of 64 threads)
__global__ void k_prep(const float* __restrict__ emb, const float* __restrict__ W1) {
    int j = threadIdx.x;
    float a = 0.f;
    #pragma unroll
    for (int k = 0; k < DH; k++) a = fmaf(emb[k], W1[k * DH + j], a);
    d_v[j] = a;
}

// 3) dinv = rsqrt(deg + 1)
__global__ void k_dinv(int N) {
    int i = blockIdx.x * blockDim.x + threadIdx.x;
    if (i < N) d_dinv[i] = rsqrtf((float)d_deg[i] + 1.0f);
}

// 4) S[dst] += dinv[src]
__global__ void k_S(const int* __restrict__ ei, int E) {
    int e = blockIdx.x * blockDim.x + threadIdx.x;
    if (e < E) atomicAdd(&d_S[ei[E + e]], d_dinv[ei[e]]);
}

// 5) Per node: c = dinv*(S+dinv); h1 = relu(c*v + b1);
//    g[i] = dinv[i] * (h1 @ W2)
__global__ __launch_bounds__(256) void k_node(const float* __restrict__ W2,
                                              const float* __restrict__ b1, int N) {
    __shared__ float sW2[DH * DH];
    __shared__ float sv[DH], sb1[DH];
    for (int t = threadIdx.x; t < DH * DH; t += blockDim.x) sW2[t] = W2[t];
    if (threadIdx.x < DH) { sv[threadIdx.x] = d_v[threadIdx.x]; sb1[threadIdx.x] = b1[threadIdx.x]; }
    __syncthreads();
    int i = blockIdx.x * blockDim.x + threadIdx.x;
    if (i >= N) return;
    float di = d_dinv[i];
    float c  = di * (d_S[i] + di);
    float acc[DH];
    #pragma unroll
    for (int j = 0; j < DH; j++) acc[j] = 0.f;
    #pragma unroll 8
    for (int d = 0; d < DH; d++) {
        float h = fmaxf(fmaf(c, sv[d], sb1[d]), 0.f);
        const float4* row = (const float4*)&sW2[d * DH];   // uniform addr -> LDS broadcast
        #pragma unroll
        for (int j4 = 0; j4 < DH / 4; j4++) {
            float4 w = row[j4];
            acc[j4 * 4 + 0] = fmaf(h, w.x, acc[j4 * 4 + 0]);
            acc[j4 * 4 + 1] = fmaf(h, w.y, acc[j4 * 4 + 1]);
            acc[j4 * 4 + 2] = fmaf(h, w.z, acc[j4 * 4 + 2]);
            acc[j4 * 4 + 3] = fmaf(h, w.w, acc[j4 * 4 + 3]);
        }
    }
    float4* gout = (float4*)&d_g[(size_t)i * DH];
    #pragma unroll
    for (int j4 = 0; j4 < DH / 4; j4++)
        gout[j4] = make_float4(di * acc[j4 * 4 + 0], di * acc[j4 * 4 + 1],
                               di * acc[j4 * 4 + 2], di * acc[j4 * 4 + 3]);
}

// 6) Edge aggregation: A[dst] += g[src]. 16 threads per edge, float4 RED.
__global__ __launch_bounds__(256) void k_edge(const int* __restrict__ ei, int E) {
    long long t = (long long)blockIdx.x * blockDim.x + threadIdx.x;
    int e = (int)(t >> 4);
    if (e >= E) return;
    int q = (int)(t & 15);
    int s = ei[e];
    int d = ei[E + e];
    float4 gv = *(const float4*)&d_g[(size_t)s * DH + q * 4];
    atomicAdd((float4*)&d_Asum[(size_t)d * DH + q * 4], gv);
}

// 7) Graph boundaries from sorted batch
__global__ void k_bounds(const int* __restrict__ batch, int N, int Gn) {
    int i = blockIdx.x * blockDim.x + threadIdx.x;
    if (i > N) return;
    int cur  = (i < N) ? batch[i] : Gn;
    int prev = (i == 0) ? -1 : batch[i - 1];
    for (int g = prev + 1; g <= cur; g++) d_gstart[g] = i;
}

// 8) Fused: h2 = relu(dinv*(A + g) + b2); per-graph mean pool; FC -> out
__global__ __launch_bounds__(256) void k_pool(const float* __restrict__ b2,
                                              const float* __restrict__ fcW,
                                              const float* __restrict__ fcb,
                                              float* __restrict__ out) {
    int g = blockIdx.x;
    int s = d_gstart[g], e = d_gstart[g + 1];
    int f   = threadIdx.x & (DH - 1);
    int grp = threadIdx.x >> 6;          // 4 groups of 64 threads
    float bb = b2[f];
    float acc = 0.f;
    for (int i = s + grp; i < e; i += 4) {
        float di = d_dinv[i];
        float val = fmaf(di, d_Asum[(size_t)i * DH + f] + d_g[(size_t)i * DH + f], bb);
        acc += fmaxf(val, 0.f);
    }
    __shared__ float sp[4 * DH];
    sp[grp * DH + f] = acc;
    __syncthreads();
    if (threadIdx.x < DH) {
        float tot = sp[f] + sp[DH + f] + sp[2 * DH + f] + sp[3 * DH + f];
        float cnt = (float)(e - s);
        sp[f] = tot / fmaxf(cnt, 1.0f);
    }
    __syncthreads();
    if (threadIdx.x < DOUT) {
        int o = threadIdx.x;
        float r = fcb[o];
        #pragma unroll
        for (int f2 = 0; f2 < DH; f2++) r = fmaf(sp[f2], fcW[f2 * DOUT + o], r);
        out[g * DOUT + o] = r;
    }
}

extern "C" void kernel_launch(void* const* d_in, const int* in_sizes, int n_in,
                              void* d_out, int out_size) {
    // metadata order: x, edge_index, batch, emb, W1, b1, W2, b2, fcW, fcb
    const int*   ei    = (const int*)d_in[1];
    const int*   batch = (const int*)d_in[2];
    const float* emb   = (const float*)d_in[3];
    const float* W1    = (const float*)d_in[4];
    const float* b1    = (const float*)d_in[5];
    const float* W2    = (const float*)d_in[6];
    const float* b2    = (const float*)d_in[7];
    const float* fcW   = (const float*)d_in[8];
    const float* fcb   = (const float*)d_in[9];
    float* out = (float*)d_out;

    int N = in_sizes[0];
    int E = in_sizes[1] / 2;
    int G = out_size / DOUT;

    int tb = 256;
    k_zero<<<(N * (DH / 4) + tb - 1) / tb, tb>>>(N);
    k_deg<<<(E + tb - 1) / tb, tb>>>(ei, E);
    k_prep<<<1, DH>>>(emb, W1);
    k_dinv<<<(N + tb - 1) / tb, tb>>>(N);
    k_S<<<(E + tb - 1) / tb, tb>>>(ei, E);
    k_node<<<(N + tb - 1) / tb, tb>>>(W2, b1, N);
    k_bounds<<<(N + 1 + tb - 1) / tb, tb>>>(batch, N, G);
    {
        long long tot = (long long)E * 16;
        int blocks = (int)((tot + tb - 1) / tb);
        k_edge<<<blocks, tb>>>(ei, E);
    }
    k_pool<<<G, tb>>>(b2, fcW, fcb, out);
}

// round 2
// speedup vs baseline: 2.0174x; 2.0174x over previous
#include <cuda_runtime.h>
#include <cuda_bf16.h>

#define NMAX 100000
#define DH   64
#define GMAX 64
#define DOUT 32
#define BMAX 65   // <= 64 thresholds -> <= 65 buckets

// ---- scratch (__device__ globals; no allocation allowed) -------------------
__device__ __align__(256) float2 d_pq[(size_t)BMAX * NMAX];  // (p,q) accum, layout [b][i]
__device__ __align__(256) float4 d_h2[(size_t)16 * NMAX];    // h2 transposed [j4][i]
__device__ __align__(256) float4 d_ninfo[NMAX];              // (a=dinv*c, dinv, bits(b), 0)
__device__ float d_S[NMAX];        // S, then reused as c
__device__ float d_dinv[NMAX];
__device__ int   d_deg[NMAX];
__device__ float d_v[DH];          // emb[0] @ W1
__device__ float d_u[BMAX * DH];   // (v .* mask_b) @ W2
__device__ float d_w[BMAX * DH];   // (b1 .* mask_b) @ W2
__device__ float d_tsort[DH];
__device__ int   d_Beff;
__device__ unsigned d_cminb, d_cmaxb;
__device__ int   d_gstart[GMAX + 2];

// ---------------------------------------------------------------------------
// 0) fused init: zero pq (worst case), zero deg/S, init c-min/max, v = emb@W1
__global__ __launch_bounds__(256) void k_init(const float* __restrict__ emb,
                                              const float* __restrict__ W1, int N) {
    int i = blockIdx.x * blockDim.x + threadIdx.x;
    int P4 = (BMAX * N + 1) / 2;          // float4 count covering BMAX*N float2
    if (i < P4) ((float4*)d_pq)[i] = make_float4(0.f, 0.f, 0.f, 0.f);
    if (i < N) { d_deg[i] = 0; d_S[i] = 0.f; }
    if (i == 0) { d_cminb = 0x7f800000u; d_cmaxb = 0u; }
    if (blockIdx.x == 0 && threadIdx.x < DH) {
        int j = threadIdx.x;
        float a = 0.f;
        #pragma unroll
        for (int k = 0; k < DH; k++) a = fmaf(emb[k], W1[k * DH + j], a);
        d_v[j] = a;
    }
}

// 1) in-degree on dst
__global__ void k_deg(const int* __restrict__ ei, int E) {
    int e = blockIdx.x * blockDim.x + threadIdx.x;
    if (e < E) atomicAdd(&d_deg[ei[E + e]], 1);
}

// 2) S[dst] += rsqrt(deg[src]+1)
__global__ void k_S(const int* __restrict__ ei, int E) {
    int e = blockIdx.x * blockDim.x + threadIdx.x;
    if (e < E) {
        float ds = rsqrtf((float)d_deg[ei[e]] + 1.0f);
        atomicAdd(&d_S[ei[E + e]], ds);
    }
}

// 3) per node: dinv, c = dinv*(S+dinv); global min/max of c
__global__ __launch_bounds__(256) void k_c(int N) {
    int i = blockIdx.x * blockDim.x + threadIdx.x;
    bool valid = (i < N);
    float dv = 0.f, c = 0.f;
    if (valid) {
        dv = rsqrtf((float)d_deg[i] + 1.0f);
        c  = dv * (d_S[i] + dv);
    }
    unsigned cb = __float_as_uint(c);              // c > 0 -> bits order == float order
    unsigned mn = __reduce_min_sync(0xffffffffu, valid ? cb : 0x7f800000u);
    unsigned mx = __reduce_max_sync(0xffffffffu, valid ? cb : 0u);
    if ((threadIdx.x & 31) == 0) {
        atomicMin(&d_cminb, mn);
        atomicMax(&d_cmaxb, mx);
    }
    if (valid) { d_dinv[i] = dv; d_S[i] = c; }     // reuse S slot as c
}

// 4) single block: sort in-range relu thresholds; build u_b, w_b per bucket
__global__ __launch_bounds__(256) void k_thresh(const float* __restrict__ b1,
                                                const float* __restrict__ W2) {
    __shared__ float sv[DH], sb1[DH], st[DH], ssort[DH];
    __shared__ int sinr[DH], scnt;
    int t = threadIdx.x;
    if (t < DH) { sv[t] = d_v[t]; sb1[t] = b1[t]; }
    __syncthreads();
    float cmin = __uint_as_float(d_cminb);
    float cmax = __uint_as_float(d_cmaxb);
    if (t < DH) {
        float vv = sv[t];
        float th = -sb1[t] / vv;                   // NaN/inf auto-fail range test
        int inr = (vv != 0.f) && (th > cmin) && (th < cmax);
        st[t] = th; sinr[t] = inr;
    }
    __syncthreads();
    if (t < DH && sinr[t]) {
        float th = st[t]; int r = 0;
        for (int d = 0; d < DH; d++)
            if (sinr[d] && (st[d] < th || (st[d] == th && d < t))) r++;
        ssort[r] = th;
    }
    if (t == 0) {
        int c = 0;
        for (int d = 0; d < DH; d++) c += sinr[d];
        scnt = c; d_Beff = c + 1;
    }
    __syncthreads();
    int cnt = scnt;
    if (t < cnt) d_tsort[t] = ssort[t];
    for (int task = t; task < BMAX * DH; task += 256) {
        int b = task >> 6, j = task & 63;
        if (b > cnt) continue;
        float lo = (b == 0)   ? cmin : ssort[b - 1];
        float hi = (b == cnt) ? cmax : ssort[b];
        float rep = 0.5f * (lo + hi);
        float uu = 0.f, ww = 0.f;
        for (int d = 0; d < DH; d++) {
            if (fmaf(rep, sv[d], sb1[d]) > 0.f) {  // relu active at representative c
                float wdj = W2[d * DH + j];
                uu = fmaf(sv[d], wdj, uu);
                ww = fmaf(sb1[d], wdj, ww);
            }
        }
        d_u[b * DH + j] = uu;
        d_w[b * DH + j] = ww;
    }
}

// 5) per node: bucket id, node info, self contribution into pq; graph bounds
__global__ __launch_bounds__(256) void k_bucket(const int* __restrict__ batch,
                                                int N, int G) {
    __shared__ float ts[DH];
    __shared__ int scnt;
    if (threadIdx.x == 0) scnt = d_Beff - 1;
    if (threadIdx.x < DH) ts[threadIdx.x] = d_tsort[threadIdx.x];
    __syncthreads();
    int i = blockIdx.x * blockDim.x + threadIdx.x;
    int cnt = scnt;
    if (i < N) {
        float c = d_S[i];
        float dv = d_dinv[i];
        int b = 0;
        for (int k = 0; k < cnt; k++) b += (ts[k] < c);
        float a = dv * c;
        d_pq[(size_t)b * N + i] = make_float2(a, dv);      // self-loop term
        d_ninfo[i] = make_float4(a, dv, __int_as_float(b), 0.f);
    }
    if (i <= N) {
        int cur  = (i < N) ? batch[i] : G;
        int prev = (i == 0) ? -1 : batch[i - 1];
        for (int g = prev + 1; g <= cur; g++) d_gstart[g] = i;
    }
}

// 6) edge aggregation: 8 bytes of RED per edge (instead of 256B float4 RED)
__global__ __launch_bounds__(256) void k_edge(const int* __restrict__ ei, int E, int N) {
    int e = blockIdx.x * blockDim.x + threadIdx.x;
    if (e >= E) return;
    int s = ei[e];
    int d = ei[E + e];
    float4 ni = d_ninfo[s];
    int b = __float_as_int(ni.z);
    atomicAdd(&d_pq[(size_t)b * N + d], make_float2(ni.x, ni.y));
}

// 7) per node: h2 = relu(dinv * sum_b (p*u_b + q*w_b) + b2), transposed store
__global__ __launch_bounds__(256) void k_out(const float* __restrict__ b2, int N) {
    __shared__ float su[BMAX * DH], sw[BMAX * DH], sb2[DH];
    int Beff = d_Beff;
    for (int t = threadIdx.x; t < Beff * DH; t += 256) { su[t] = d_u[t]; sw[t] = d_w[t]; }
    if (threadIdx.x < DH) sb2[threadIdx.x] = b2[threadIdx.x];
    __syncthreads();
    int idx = blockIdx.x * blockDim.x + threadIdx.x;
    int i = idx >> 2;
    int part = idx & 3;                 // 4 threads per node, 16 features each
    if (i >= N) return;
    float dv = d_dinv[i];
    float acc[16];
    #pragma unroll
    for (int k = 0; k < 16; k++) acc[k] = 0.f;
    for (int b = 0; b < Beff; b++) {
        float2 pq = d_pq[(size_t)b * N + i];
        if (pq.x != 0.f || pq.y != 0.f) {
            const float4* u4 = (const float4*)&su[b * DH + part * 16];
            const float4* w4 = (const float4*)&sw[b * DH + part * 16];
            #pragma unroll
            for (int jj = 0; jj < 4; jj++) {
                float4 u = u4[jj], w = w4[jj];
                acc[jj * 4 + 0] = fmaf(pq.x, u.x, fmaf(pq.y, w.x, acc[jj * 4 + 0]));
                acc[jj * 4 + 1] = fmaf(pq.x, u.y, fmaf(pq.y, w.y, acc[jj * 4 + 1]));
                acc[jj * 4 + 2] = fmaf(pq.x, u.z, fmaf(pq.y, w.z, acc[jj * 4 + 2]));
                acc[jj * 4 + 3] = fmaf(pq.x, u.w, fmaf(pq.y, w.w, acc[jj * 4 + 3]));
            }
        }
    }
    #pragma unroll
    for (int jj = 0; jj < 4; jj++) {
        int j0 = part * 16 + jj * 4;
        float4 o;
        o.x = fmaxf(fmaf(dv, acc[jj * 4 + 0], sb2[j0 + 0]), 0.f);
        o.y = fmaxf(fmaf(dv, acc[jj * 4 + 1], sb2[j0 + 1]), 0.f);
        o.z = fmaxf(fmaf(dv, acc[jj * 4 + 2], sb2[j0 + 2]), 0.f);
        o.w = fmaxf(fmaf(dv, acc[jj * 4 + 3], sb2[j0 + 3]), 0.f);
        d_h2[(size_t)(part * 4 + jj) * N + i] = o;
    }
}

// 8) per-graph mean pool + FC
__global__ __launch_bounds__(256) void k_pool(const float* __restrict__ fcW,
                                              const float* __restrict__ fcb,
                                              float* __restrict__ out, int N) {
    int g = blockIdx.x;
    int s = d_gstart[g], e = d_gstart[g + 1];
    int f4 = threadIdx.x & 15;
    int strm = threadIdx.x >> 4;
    float4 acc = make_float4(0.f, 0.f, 0.f, 0.f);
    for (int i = s + strm; i < e; i += 16) {
        float4 v = d_h2[(size_t)f4 * N + i];
        acc.x += v.x; acc.y += v.y; acc.z += v.z; acc.w += v.w;
    }
    __shared__ float4 sp[256];
    __shared__ float pooled[DH];
    sp[threadIdx.x] = acc;
    __syncthreads();
    if (threadIdx.x < 16) {
        float4 tot = sp[threadIdx.x];
        for (int k = 1; k < 16; k++) {
            float4 v = sp[k * 16 + threadIdx.x];
            tot.x += v.x; tot.y += v.y; tot.z += v.z; tot.w += v.w;
        }
        float inv = 1.f / fmaxf((float)(e - s), 1.f);
        pooled[threadIdx.x * 4 + 0] = tot.x * inv;
        pooled[threadIdx.x * 4 + 1] = tot.y * inv;
        pooled[threadIdx.x * 4 + 2] = tot.z * inv;
        pooled[threadIdx.x * 4 + 3] = tot.w * inv;
    }
    __syncthreads();
    if (threadIdx.x < DOUT) {
        int o = threadIdx.x;
        float r = fcb[o];
        #pragma unroll
        for (int f = 0; f < DH; f++) r = fmaf(pooled[f], fcW[f * DOUT + o], r);
        out[g * DOUT + o] = r;
    }
}

extern "C" void kernel_launch(void* const* d_in, const int* in_sizes, int n_in,
                              void* d_out, int out_size) {
    // metadata order: x, edge_index, batch, emb, W1, b1, W2, b2, fcW, fcb
    const int*   ei    = (const int*)d_in[1];
    const int*   batch = (const int*)d_in[2];
    const float* emb   = (const float*)d_in[3];
    const float* W1    = (const float*)d_in[4];
    const float* b1    = (const float*)d_in[5];
    const float* W2    = (const float*)d_in[6];
    const float* b2    = (const float*)d_in[7];
    const float* fcW   = (const float*)d_in[8];
    const float* fcb   = (const float*)d_in[9];
    float* out = (float*)d_out;

    int N = in_sizes[0];
    int E = in_sizes[1] / 2;
    int G = out_size / DOUT;

    const int tb = 256;
    int P4 = (BMAX * N + 1) / 2;                  // float4 zero tasks for pq
    int initN = P4 > N ? P4 : N;

    k_init<<<(initN + tb - 1) / tb, tb>>>(emb, W1, N);
    k_deg<<<(E + tb - 1) / tb, tb>>>(ei, E);
    k_S<<<(E + tb - 1) / tb, tb>>>(ei, E);
    k_c<<<(N + tb - 1) / tb, tb>>>(N);
    k_thresh<<<1, tb>>>(b1, W2);
    k_bucket<<<(N + 1 + tb - 1) / tb, tb>>>(batch, N, G);
    k_edge<<<(E + tb - 1) / tb, tb>>>(ei, E, N);
    k_out<<<(4 * N + tb - 1) / tb, tb>>>(b2, N);
    k_pool<<<G, tb>>>(fcW, fcb, out, N);
}

// round 3
// speedup vs baseline: 2.2391x; 1.1099x over previous
#include <cuda_runtime.h>
#include <cuda_bf16.h>

#define NMAX 100000
#define DH   64
#define GMAX 64
#define DOUT 32
#define BMAX 65   // <= 64 thresholds -> <= 65 buckets

// ---- scratch (__device__ globals; no allocation allowed) -------------------
__device__ __align__(256) float2 d_pq[(size_t)BMAX * NMAX];  // (p,q), layout [b][i]
__device__ __align__(256) float4 d_ninfo[NMAX];              // (a=dinv*c, dinv, bits(b), 0)
__device__ float d_S[NMAX];          // S, then reused as c
__device__ float d_dinv[NMAX];
__device__ int   d_deg[NMAX];
__device__ float d_u[BMAX * DH];     // (v .* mask_b) @ W2
__device__ float d_w[BMAX * DH];     // (b1 .* mask_b) @ W2
__device__ float d_tsort[DH];
__device__ int   d_Beff;
__device__ unsigned d_cminb, d_cmaxb;
__device__ int   d_gstart[GMAX + 2];
__device__ float d_pooled[GMAX * DH];

// ---------------------------------------------------------------------------
// 0) zero deg, S, pooled, min/max
__global__ __launch_bounds__(256) void k_init(int N) {
    int i = blockIdx.x * blockDim.x + threadIdx.x;
    if (i < N) { d_deg[i] = 0; d_S[i] = 0.f; }
    if (i < GMAX * DH) d_pooled[i] = 0.f;
    if (i == 0) { d_cminb = 0x7f800000u; d_cmaxb = 0u; }
}

// 1) in-degree on dst
__global__ void k_deg(const int* __restrict__ ei, int E) {
    int e = blockIdx.x * blockDim.x + threadIdx.x;
    if (e < E) atomicAdd(&d_deg[ei[E + e]], 1);
}

// 2) S[dst] += rsqrt(deg[src]+1)
__global__ void k_S(const int* __restrict__ ei, int E) {
    int e = blockIdx.x * blockDim.x + threadIdx.x;
    if (e < E) {
        float ds = rsqrtf((float)d_deg[ei[e]] + 1.0f);
        atomicAdd(&d_S[ei[E + e]], ds);
    }
}

// 3) per node: dinv, c = dinv*(S+dinv); global min/max of c
__global__ __launch_bounds__(256) void k_c(int N) {
    int i = blockIdx.x * blockDim.x + threadIdx.x;
    bool valid = (i < N);
    float dv = 0.f, c = 0.f;
    if (valid) {
        dv = rsqrtf((float)d_deg[i] + 1.0f);
        c  = dv * (d_S[i] + dv);
    }
    unsigned cb = __float_as_uint(c);              // c > 0 -> bit order == float order
    unsigned mn = __reduce_min_sync(0xffffffffu, valid ? cb : 0x7f800000u);
    unsigned mx = __reduce_max_sync(0xffffffffu, valid ? cb : 0u);
    if ((threadIdx.x & 31) == 0) {
        atomicMin(&d_cminb, mn);
        atomicMax(&d_cmaxb, mx);
    }
    if (valid) { d_dinv[i] = dv; d_S[i] = c; }     // reuse S slot as c
}

// 4) single block: v = emb@W1; sort in-range thresholds; build u_b, w_b
__global__ __launch_bounds__(256) void k_thresh(const float* __restrict__ emb,
                                                const float* __restrict__ W1,
                                                const float* __restrict__ b1,
                                                const float* __restrict__ W2) {
    __shared__ float sv[DH], sb1[DH], st[DH], ssort[DH];
    __shared__ int sinr[DH], scnt;
    int t = threadIdx.x;
    if (t < DH) {
        float a = 0.f;
        #pragma unroll
        for (int k = 0; k < DH; k++) a = fmaf(emb[k], W1[k * DH + t], a);
        sv[t] = a; sb1[t] = b1[t];
    }
    __syncthreads();
    float cmin = __uint_as_float(d_cminb);
    float cmax = __uint_as_float(d_cmaxb);
    if (t < DH) {
        float vv = sv[t];
        float th = -sb1[t] / vv;                   // NaN/inf auto-fail range test
        int inr = (vv != 0.f) && (th > cmin) && (th < cmax);
        st[t] = th; sinr[t] = inr;
    }
    __syncthreads();
    if (t < DH && sinr[t]) {
        float th = st[t]; int r = 0;
        for (int d = 0; d < DH; d++)
            if (sinr[d] && (st[d] < th || (st[d] == th && d < t))) r++;
        ssort[r] = th;
    }
    if (t == 0) {
        int c = 0;
        for (int d = 0; d < DH; d++) c += sinr[d];
        scnt = c; d_Beff = c + 1;
    }
    __syncthreads();
    int cnt = scnt;
    if (t < cnt) d_tsort[t] = ssort[t];
    for (int task = t; task < BMAX * DH; task += 256) {
        int b = task >> 6, j = task & 63;
        if (b > cnt) continue;
        float lo = (b == 0)   ? cmin : ssort[b - 1];
        float hi = (b == cnt) ? cmax : ssort[b];
        float rep = 0.5f * (lo + hi);
        float uu = 0.f, ww = 0.f;
        for (int d = 0; d < DH; d++) {
            if (fmaf(rep, sv[d], sb1[d]) > 0.f) {
                float wdj = W2[d * DH + j];
                uu = fmaf(sv[d], wdj, uu);
                ww = fmaf(sb1[d], wdj, ww);
            }
        }
        d_u[b * DH + j] = uu;
        d_w[b * DH + j] = ww;
    }
}

// 5) per node: bucket id, ninfo; graph bounds
__global__ __launch_bounds__(256) void k_bucket(const int* __restrict__ batch,
                                                int N, int G) {
    __shared__ float ts[DH];
    __shared__ int scnt;
    if (threadIdx.x == 0) scnt = d_Beff - 1;
    if (threadIdx.x < DH) ts[threadIdx.x] = d_tsort[threadIdx.x];
    __syncthreads();
    int i = blockIdx.x * blockDim.x + threadIdx.x;
    int cnt = scnt;
    if (i < N) {
        float c = d_S[i];
        float dv = d_dinv[i];
        int b = 0;
        for (int k = 0; k < cnt; k++) b += (ts[k] < c);
        d_ninfo[i] = make_float4(dv * c, dv, __int_as_float(b), 0.f);
    }
    if (i <= N) {
        int cur  = (i < N) ? batch[i] : G;
        int prev = (i == 0) ? -1 : batch[i - 1];
        for (int g = prev + 1; g <= cur; g++) d_gstart[g] = i;
    }
}

// 6) init pq rows [0, Beff): self term on own bucket row, zero elsewhere
__global__ __launch_bounds__(256) void k_pqinit(int N) {
    int b = blockIdx.y;
    if (b >= d_Beff) return;
    int i = blockIdx.x * blockDim.x + threadIdx.x;
    if (i >= N) return;
    float4 ni = d_ninfo[i];
    int bi = __float_as_int(ni.z);
    d_pq[(size_t)b * N + i] = (b == bi) ? make_float2(ni.x, ni.y)
                                        : make_float2(0.f, 0.f);
}

// 7) edge aggregation: 8-byte float2 RED per edge
__global__ __launch_bounds__(256) void k_edge(const int* __restrict__ ei, int E, int N) {
    int e = blockIdx.x * blockDim.x + threadIdx.x;
    if (e >= E) return;
    int s = ei[e];
    int d = ei[E + e];
    float4 ni = d_ninfo[s];
    int b = __float_as_int(ni.z);
    atomicAdd(&d_pq[(size_t)b * N + d], make_float2(ni.x, ni.y));
}

// 8) per node: h2 = relu(dinv * sum_b (p*u_b + q*w_b) + b2); fused mean-pool
//    partial sums via shuffle-tree + global atomics into d_pooled.
__global__ __launch_bounds__(256) void k_out(const int* __restrict__ batch,
                                             const float* __restrict__ b2, int N) {
    __shared__ float su[BMAX * DH];
    __shared__ float sw[BMAX * DH];
    __shared__ float swarp[8][DH];
    __shared__ float sb2[DH];
    __shared__ int sg0;
    int t = threadIdx.x;
    int Beff = d_Beff;
    for (int k = t; k < Beff * DH; k += 256) { su[k] = d_u[k]; sw[k] = d_w[k]; }
    if (t < DH) sb2[t] = b2[t];
    int i0 = blockIdx.x * 64;
    if (t == 0) sg0 = batch[i0];
    __syncthreads();

    int node = i0 + (t >> 2);
    int part = t & 3;
    int g0 = sg0;

    float acc[16];
    #pragma unroll
    for (int k = 0; k < 16; k++) acc[k] = 0.f;
    float dv = 0.f;
    int g = g0;
    if (node < N) {
        dv = d_dinv[node];
        g = batch[node];
        for (int b = 0; b < Beff; b++) {
            float2 pq = d_pq[(size_t)b * N + node];
            if (pq.y != 0.f) {
                const float4* u4 = (const float4*)&su[b * DH + part * 16];
                const float4* w4 = (const float4*)&sw[b * DH + part * 16];
                #pragma unroll
                for (int jj = 0; jj < 4; jj++) {
                    float4 u = u4[jj], w = w4[jj];
                    acc[jj * 4 + 0] = fmaf(pq.x, u.x, fmaf(pq.y, w.x, acc[jj * 4 + 0]));
                    acc[jj * 4 + 1] = fmaf(pq.x, u.y, fmaf(pq.y, w.y, acc[jj * 4 + 1]));
                    acc[jj * 4 + 2] = fmaf(pq.x, u.z, fmaf(pq.y, w.z, acc[jj * 4 + 2]));
                    acc[jj * 4 + 3] = fmaf(pq.x, u.w, fmaf(pq.y, w.w, acc[jj * 4 + 3]));
                }
            }
        }
    }
    // h2 features for this (node, part)
    float h[16];
    #pragma unroll
    for (int k = 0; k < 16; k++)
        h[k] = (node < N) ? fmaxf(fmaf(dv, acc[k], sb2[part * 16 + k]), 0.f) : 0.f;

    // minority path: node belongs to a different graph than block leader
    if (node < N && g != g0) {
        #pragma unroll
        for (int k = 0; k < 16; k++)
            atomicAdd(&d_pooled[g * DH + part * 16 + k], h[k]);
        #pragma unroll
        for (int k = 0; k < 16; k++) h[k] = 0.f;
    }
    // shuffle-reduce over node dimension within warp (8 nodes)
    #pragma unroll
    for (int k = 0; k < 16; k++) {
        h[k] += __shfl_xor_sync(0xffffffffu, h[k], 16);
        h[k] += __shfl_xor_sync(0xffffffffu, h[k], 8);
        h[k] += __shfl_xor_sync(0xffffffffu, h[k], 4);
    }
    int lane = t & 31, warp = t >> 5;
    if (lane < 4) {
        #pragma unroll
        for (int k = 0; k < 16; k++) swarp[warp][lane * 16 + k] = h[k];
    }
    __syncthreads();
    if (t < DH) {
        float tot = 0.f;
        #pragma unroll
        for (int wq = 0; wq < 8; wq++) tot += swarp[wq][t];
        atomicAdd(&d_pooled[g0 * DH + t], tot);
    }
}

// 9) per graph: mean + FC
__global__ __launch_bounds__(64) void k_pool(const float* __restrict__ fcW,
                                             const float* __restrict__ fcb,
                                             float* __restrict__ out) {
    int g = blockIdx.x;
    __shared__ float sp[DH];
    int t = threadIdx.x;
    int cnt = d_gstart[g + 1] - d_gstart[g];
    float inv = 1.f / fmaxf((float)cnt, 1.f);
    sp[t] = d_pooled[g * DH + t] * inv;
    __syncthreads();
    if (t < DOUT) {
        float r = fcb[t];
        #pragma unroll
        for (int f = 0; f < DH; f++) r = fmaf(sp[f], fcW[f * DOUT + t], r);
        out[g * DOUT + t] = r;
    }
}

extern "C" void kernel_launch(void* const* d_in, const int* in_sizes, int n_in,
                              void* d_out, int out_size) {
    // metadata order: x, edge_index, batch, emb, W1, b1, W2, b2, fcW, fcb
    const int*   ei    = (const int*)d_in[1];
    const int*   batch = (const int*)d_in[2];
    const float* emb   = (const float*)d_in[3];
    const float* W1    = (const float*)d_in[4];
    const float* b1    = (const float*)d_in[5];
    const float* W2    = (const float*)d_in[6];
    const float* b2    = (const float*)d_in[7];
    const float* fcW   = (const float*)d_in[8];
    const float* fcb   = (const float*)d_in[9];
    float* out = (float*)d_out;

    int N = in_sizes[0];
    int E = in_sizes[1] / 2;
    int G = out_size / DOUT;

    const int tb = 256;
    k_init<<<(N + tb - 1) / tb, tb>>>(N);
    k_deg<<<(E + tb - 1) / tb, tb>>>(ei, E);
    k_S<<<(E + tb - 1) / tb, tb>>>(ei, E);
    k_c<<<(N + tb - 1) / tb, tb>>>(N);
    k_thresh<<<1, tb>>>(emb, W1, b1, W2);
    k_bucket<<<(N + 1 + tb - 1) / tb, tb>>>(batch, N, G);
    {
        dim3 grid((N + tb - 1) / tb, BMAX);
        k_pqinit<<<grid, tb>>>(N);
    }
    k_edge<<<(E + tb - 1) / tb, tb>>>(ei, E, N);
    k_out<<<(N + 63) / 64, tb>>>(batch, b2, N);
    k_pool<<<G, 64>>>(fcW, fcb, out);
}